// round 16
// baseline (speedup 1.0000x reference)
#include <cuda_runtime.h>
#include <stdint.h>

#define DIM 64
#define MAXN 50048
#define CAP 64
#define OVF_CAP 8192

// __device__ global scratch (sanctioned — no dynamic allocation). ~12.8 MB.
__device__ int g_cnt[MAXN];
__device__ int g_bucket[(size_t)MAXN * CAP];
__device__ int g_ovf_cnt;
__device__ int g_ovf[OVF_CAP];

__global__ void reset_kernel(int n_nodes) {
    int i = blockIdx.x * blockDim.x + threadIdx.x;
    if (i < n_nodes) g_cnt[i] = 0;
    if (i == 0) g_ovf_cnt = 0;
}

__global__ void place_kernel(const int* __restrict__ dst, int n_edges) {
    int e = blockIdx.x * blockDim.x + threadIdx.x;
    if (e >= n_edges) return;
    int d = dst[e];
    int pos = atomicAdd(&g_cnt[d], 1);
    if (pos < CAP) {
        g_bucket[(size_t)d * CAP + pos] = e;
    } else {
        int o = atomicAdd(&g_ovf_cnt, 1);
        if (o < OVF_CAP) g_ovf[o] = e;
    }
}

// One warp per node. 2 groups of 16 lanes; each group processes one edge per
// iteration, each lane owns 4 dims (one float4). Depth-3 software pipeline:
//   stage C: bucket entry e          (issued 2 iters before use)
//   stage B: s = src[e]              (issued 1 iter before use)
//   stage A: embedding rows + math   (loads issued 1 iter before consumption)
__global__ __launch_bounds__(256)
void node_kernel(const float* __restrict__ node_emb,
                 const float* __restrict__ edge_emb,
                 const int* __restrict__ src,
                 float* __restrict__ h_out,
                 float* __restrict__ dr_out,
                 int n_nodes) {
    int wid  = threadIdx.x >> 5;
    int node = blockIdx.x * 8 + wid;
    if (node >= n_nodes) return;          // warp-uniform exit
    int lane = threadIdx.x & 31;
    int g    = lane >> 4;                 // 0 or 1
    int l    = lane & 15;                 // 0..15

    int cnt = g_cnt[node];
    if (cnt > CAP) cnt = CAP;

    float4* op = reinterpret_cast<float4*>(h_out + (size_t)node * DIM);
    if (cnt == 0) {                       // warp-uniform: store zero row
        if (g == 0) op[l] = make_float4(0.f, 0.f, 0.f, 0.f);
        return;
    }

    float4 tt = reinterpret_cast<const float4*>(node_emb + (size_t)node * DIM)[l];
    float4 acc = make_float4(0.f, 0.f, 0.f, 0.f);

    const int* bptr = g_bucket + (size_t)node * CAP;
    int iters = (cnt + 1) >> 1;
    int cm1   = cnt - 1;

    // ---- pipeline prologue ----
    int idxA = g;
    int eA = bptr[min(idxA, cm1)];
    int sA = src[eA];
    float4 hA = reinterpret_cast<const float4*>(node_emb + (size_t)sA * DIM)[l];
    float4 rA = reinterpret_cast<const float4*>(edge_emb + (size_t)eA * DIM)[l];

    int idxB = idxA + 2;
    int eB = bptr[min(idxB, cm1)];
    int sB = src[eB];

    int idxC = idxB + 2;
    int eC = bptr[min(idxC, cm1)];

    for (int j = 0; j < iters; j++) {
        // ---- prefetch (consumed NEXT iteration) ----
        float4 hB = reinterpret_cast<const float4*>(node_emb + (size_t)sB * DIM)[l];
        float4 rB = reinterpret_cast<const float4*>(edge_emb + (size_t)eB * DIM)[l];
        int sC   = src[eC];
        int idxD = idxC + 2;
        int eD   = bptr[min(idxD, cm1)];

        // ---- compute stage A (data arrived last iteration) ----
        float m0 = hA.x * rA.x;
        float m1 = hA.y * rA.y;
        float m2 = hA.z * rA.z;
        float m3 = hA.w * rA.w;
        float p = m0 * tt.x;
        p = fmaf(m1, tt.y, p);
        p = fmaf(m2, tt.z, p);
        p = fmaf(m3, tt.w, p);

        #pragma unroll
        for (int o = 8; o > 0; o >>= 1)
            p += __shfl_xor_sync(0xffffffffu, p, o, 16);

        bool val = idxA < cnt;
        if (val && l == 0) dr_out[eA] = p;

        float sig = 1.0f / (1.0f + __expf(-p));
        if (val) {
            acc.x = fmaf(sig, m0, acc.x);
            acc.y = fmaf(sig, m1, acc.y);
            acc.z = fmaf(sig, m2, acc.z);
            acc.w = fmaf(sig, m3, acc.w);
        }

        // ---- shift pipeline ----
        idxA = idxB; eA = eB; hA = hB; rA = rB;
        idxB = idxC; eB = eC; sB = sC;
        idxC = idxD; eC = eD;
    }

    // combine the two groups' accumulators (same node, same dims)
    acc.x += __shfl_xor_sync(0xffffffffu, acc.x, 16);
    acc.y += __shfl_xor_sync(0xffffffffu, acc.y, 16);
    acc.z += __shfl_xor_sync(0xffffffffu, acc.z, 16);
    acc.w += __shfl_xor_sync(0xffffffffu, acc.w, 16);

    if (g == 0) op[l] = acc;
}

// Fallback for bucket-overflow edges (expected 0 for this input).
__global__ void ovf_kernel(const float* __restrict__ node_emb,
                           const float* __restrict__ edge_emb,
                           const int* __restrict__ src,
                           const int* __restrict__ dst,
                           float* __restrict__ h_out,
                           float* __restrict__ dr_out) {
    int n = g_ovf_cnt;
    if (n > OVF_CAP) n = OVF_CAP;
    int lane = threadIdx.x & 31;
    int l = lane & 7;
    int group   = (blockIdx.x * blockDim.x + threadIdx.x) >> 3;
    int ngroups = (gridDim.x * blockDim.x) >> 3;
    int iters = (n + ngroups - 1) / ngroups;

    for (int t = 0; t < iters; t++) {
        int i = t * ngroups + group;
        bool v = i < n;
        int e = v ? g_ovf[i] : 0;
        int s = src[e];
        int d = dst[e];

        const float4* hp = reinterpret_cast<const float4*>(node_emb + (size_t)s * DIM);
        const float4* rp = reinterpret_cast<const float4*>(edge_emb + (size_t)e * DIM);
        const float4* tp = reinterpret_cast<const float4*>(node_emb + (size_t)d * DIM);
        float4 ha = hp[l], hb = hp[l + 8];
        float4 ra = rp[l], rb = rp[l + 8];
        float4 ta = tp[l], tb = tp[l + 8];

        float m0 = ha.x * ra.x, m1 = ha.y * ra.y, m2 = ha.z * ra.z, m3 = ha.w * ra.w;
        float n0 = hb.x * rb.x, n1 = hb.y * rb.y, n2 = hb.z * rb.z, n3 = hb.w * rb.w;

        float p = m0 * ta.x;
        p = fmaf(m1, ta.y, p);
        p = fmaf(m2, ta.z, p);
        p = fmaf(m3, ta.w, p);
        p = fmaf(n0, tb.x, p);
        p = fmaf(n1, tb.y, p);
        p = fmaf(n2, tb.z, p);
        p = fmaf(n3, tb.w, p);

        #pragma unroll
        for (int o = 4; o > 0; o >>= 1)
            p += __shfl_xor_sync(0xffffffffu, p, o, 8);

        if (v && l == 0) dr_out[e] = p;

        float sig = 1.0f / (1.0f + __expf(-p));
        if (v) {
            float* hd = h_out + (size_t)d * DIM + 4 * l;
            asm volatile("red.global.add.v4.f32 [%0], {%1, %2, %3, %4};"
                         :: "l"(hd), "f"(sig * m0), "f"(sig * m1),
                            "f"(sig * m2), "f"(sig * m3) : "memory");
            asm volatile("red.global.add.v4.f32 [%0], {%1, %2, %3, %4};"
                         :: "l"(hd + 32), "f"(sig * n0), "f"(sig * n1),
                            "f"(sig * n2), "f"(sig * n3) : "memory");
        }
    }
}

extern "C" void kernel_launch(void* const* d_in, const int* in_sizes, int n_in,
                              void* d_out, int out_size) {
    const float* node_emb = (const float*)d_in[0];
    const float* edge_emb = (const float*)d_in[1];
    const int*   src      = (const int*)d_in[2];
    const int*   dst      = (const int*)d_in[3];

    int n_nodes = in_sizes[0] / DIM;
    int n_edges = in_sizes[1] / DIM;

    float* h_out  = (float*)d_out;                                // [N, D]
    float* dr_out = (float*)d_out + (size_t)n_nodes * DIM;        // [E]

    reset_kernel<<<(n_nodes + 255) / 256, 256>>>(n_nodes);
    place_kernel<<<(n_edges + 255) / 256, 256>>>(dst, n_edges);

    int node_blocks = (n_nodes + 7) / 8;   // 8 warps/block, 1 node/warp
    node_kernel<<<node_blocks, 256>>>(node_emb, edge_emb, src,
                                      h_out, dr_out, n_nodes);

    ovf_kernel<<<1, 256>>>(node_emb, edge_emb, src, dst, h_out, dr_out);
}